// round 10
// baseline (speedup 1.0000x reference)
#include <cuda_runtime.h>
#include <cstdint>
#include <cstdio>

// ---------------------------------------------------------------------------
// Problem constants
// ---------------------------------------------------------------------------
#define BN_EPS   1e-3f
#define HD       256          // hidden dim
#define G4       1024         // 4*H
#define TENC     1024         // encoder steps
#define TDEC     35           // decoder steps
#define BATCH    256
#define FEAT     8

#define CLUSTER  8            // CTAs per cluster (N-partition of gates)
#define MROWS    16           // batch rows per cluster
#define NCOLS    128          // gate columns per CTA (32 units x 4 gates)
#define NTHREADS 256

// ---------------------------------------------------------------------------
// SMEM layout (float offsets)
// ---------------------------------------------------------------------------
#define OFF_W     0                       // 64*128 float4 = 32768 floats (rk slice, [kv*128+col])
#define OFF_H     32768                   // 2 x 16 x 256 = 8192 floats (ping-pong h)
#define OFF_Z     (OFF_H + 8192)          // 16 x 128 = 2048 floats (z scratch)
#define OFF_C     (OFF_Z + 2048)          // 512 floats (c state, 16 rows x 32 units)
#define OFF_P     (OFF_C + 512)           // 2 x 128 floats (pulse double buffer)
#define OFF_WC    (OFF_P + 256)           // 8 x 128 (folded input weights slice)
#define OFF_BE    (OFF_WC + 1024)         // 128 (encoder bias slice)
#define OFF_WD    (OFF_BE + 128)          // 2 x 128 (decoder input weights slice)
#define OFF_BD    (OFF_WD + 256)          // 128 (decoder bias slice)
#define OFF_WM    (OFF_BD + 128)          // 256 x 2 (W_mlp full)
#define OFF_PRED  (OFF_WM + 512)          // 16 x 2 (pred carry)
#define OFF_MISC  (OFF_PRED + 32)         // [0:2] b_mlp, [2:4] scale_w, [4:6] scale_b
#define SMEM_FLOATS (OFF_MISC + 32)
#define SMEM_BYTES  (SMEM_FLOATS * 4)     // ~183.7 KB

// ---------------------------------------------------------------------------
// Device scratch (precomputed folded weights)
// ---------------------------------------------------------------------------
__device__ float gWc[FEAT * G4];   // diag(a) * W_pulse @ lstm_k
__device__ float gBe[G4];          // folded encoder bias (incl lstm_b)
__device__ float gWd[2 * G4];      // W_eis @ lstm_k
__device__ float gBd[G4];          // b_eis @ lstm_k + lstm_b

// ---------------------------------------------------------------------------
// Precompute kernel: fold BN + pulse_embed + input projection into K=8 matrix,
// and decoder token embedding + input projection into K=2 matrix.
// ---------------------------------------------------------------------------
__global__ void precomp_kernel(const float* __restrict__ bn_gamma,
                               const float* __restrict__ bn_beta,
                               const float* __restrict__ bn_mean,
                               const float* __restrict__ bn_var,
                               const float* __restrict__ W_pulse,   // (8,256)
                               const float* __restrict__ b_pulse,   // (256)
                               const float* __restrict__ lstm_k,    // (256,1024)
                               const float* __restrict__ lstm_b,    // (1024)
                               const float* __restrict__ W_eis,     // (2,256)
                               const float* __restrict__ b_eis)     // (256)
{
    int g = blockIdx.x * blockDim.x + threadIdx.x;
    if (g >= G4) return;

    float a[FEAT], d[FEAT];
#pragma unroll
    for (int f = 0; f < FEAT; ++f) {
        a[f] = bn_gamma[f] * rsqrtf(bn_var[f] + BN_EPS);
        d[f] = bn_beta[f] - bn_mean[f] * a[f];
    }
    float wc[FEAT];
#pragma unroll
    for (int f = 0; f < FEAT; ++f) wc[f] = 0.f;
    float be = 0.f, wd0 = 0.f, wd1 = 0.f, bd = 0.f;

    for (int k = 0; k < HD; ++k) {
        float kk = lstm_k[k * G4 + g];
        float ev = b_pulse[k];
#pragma unroll
        for (int f = 0; f < FEAT; ++f) {
            float wp = W_pulse[f * HD + k];
            wc[f] += wp * kk;
            ev    += d[f] * wp;
        }
        be  += ev * kk;
        wd0 += W_eis[k] * kk;
        wd1 += W_eis[HD + k] * kk;
        bd  += b_eis[k] * kk;
    }
#pragma unroll
    for (int f = 0; f < FEAT; ++f) gWc[f * G4 + g] = a[f] * wc[f];
    gBe[g]      = be + lstm_b[g];
    gWd[g]      = wd0;
    gWd[G4 + g] = wd1;
    gBd[g]      = bd + lstm_b[g];
}

// ---------------------------------------------------------------------------
// Helpers
// ---------------------------------------------------------------------------
__device__ __forceinline__ unsigned long long ffma2(unsigned long long a,
                                                    unsigned long long b,
                                                    unsigned long long c) {
    unsigned long long d;
    asm("fma.rn.f32x2 %0, %1, %2, %3;" : "=l"(d) : "l"(a), "l"(b), "l"(c));
    return d;
}
__device__ __forceinline__ unsigned long long pack2(float lo, float hi) {
    float2 v = make_float2(lo, hi);
    return *reinterpret_cast<unsigned long long*>(&v);
}
__device__ __forceinline__ uint32_t smem_u32(const void* p) {
    uint32_t a;
    asm("{ .reg .u64 t; cvta.to.shared.u64 t, %1; cvt.u32.u64 %0, t; }"
        : "=r"(a) : "l"(p));
    return a;
}
__device__ __forceinline__ float sigf(float x) {
    return 1.f / (1.f + __expf(-x));
}

// ---------------------------------------------------------------------------
// Main persistent LSTM kernel. Cluster of 8 CTAs; each CTA owns 32 hidden
// units (all 4 gates) for 16 batch rows. Weights SMEM-resident; h exchanged
// via DSMEM with ping-pong buffers; one cluster barrier per step.
// ---------------------------------------------------------------------------
extern __shared__ float smem[];

__global__ void __launch_bounds__(NTHREADS, 1) __cluster_dims__(CLUSTER, 1, 1)
lstm_kernel(const float* __restrict__ pulse,       // (256,1024,8)
            const float* __restrict__ lstm_rk,     // (256,1024)
            const float* __restrict__ embed_table, // (1,2)
            const float* __restrict__ W_mlp,       // (256,2)
            const float* __restrict__ b_mlp,       // (2)
            const float* __restrict__ scale_w,     // (2)
            const float* __restrict__ scale_b,     // (2)
            float* __restrict__ out)               // (256,35,2)
{
    const int tid = threadIdx.x;
    uint32_t rank;
    asm("mov.u32 %0, %%cluster_ctarank;" : "=r"(rank));
    const int cid    = blockIdx.x / CLUSTER;
    const int b_base = cid * MROWS;

    float* wsm = smem + OFF_W;
    float* hb  = smem + OFF_H;
    float* zsm = smem + OFF_Z;
    float* csm = smem + OFF_C;
    float* psm = smem + OFF_P;
    float* wcs = smem + OFF_WC;
    float* bes = smem + OFF_BE;
    float* wds = smem + OFF_WD;
    float* bds = smem + OFF_BD;
    float* wm  = smem + OFF_WM;
    float* prd = smem + OFF_PRED;
    float* msc = smem + OFF_MISC;

    // ---------------- prologue: load weights / constants into SMEM ----------
    // rk slice, layout wsm4[kv*128 + col] = {rk[4kv+j][gcol]}, gcol = gate*256 + rank*32 + u
    for (int i = tid; i < 64 * NCOLS; i += NTHREADS) {
        int kv = i >> 7, col = i & 127;
        int gcol = ((col >> 5) << 8) + (int)rank * 32 + (col & 31);
        float4 w;
        w.x = lstm_rk[(4 * kv + 0) * G4 + gcol];
        w.y = lstm_rk[(4 * kv + 1) * G4 + gcol];
        w.z = lstm_rk[(4 * kv + 2) * G4 + gcol];
        w.w = lstm_rk[(4 * kv + 3) * G4 + gcol];
        reinterpret_cast<float4*>(wsm)[i] = w;
    }
    if (tid < NCOLS) {
        int col  = tid;
        int gcol = ((col >> 5) << 8) + (int)rank * 32 + (col & 31);
        bes[col] = gBe[gcol];
        bds[col] = gBd[gcol];
        wds[col]         = gWd[gcol];
        wds[NCOLS + col] = gWd[G4 + gcol];
#pragma unroll
        for (int f = 0; f < FEAT; ++f) wcs[f * NCOLS + col] = gWc[f * G4 + gcol];
    }
    for (int i = tid; i < 512; i += NTHREADS) { wm[i] = W_mlp[i]; csm[i] = 0.f; }
    for (int i = tid; i < MROWS * HD; i += NTHREADS) hb[i] = 0.f;   // h0 = 0 (buffer 0)
    if (tid < 32) prd[tid] = embed_table[tid & 1];                  // tok0 carry
    if (tid < 2) { msc[tid] = b_mlp[tid]; msc[2 + tid] = scale_w[tid]; msc[4 + tid] = scale_b[tid]; }
    if (tid < 128)  // pulse for t=0
        psm[tid] = __ldg(&pulse[(size_t)(b_base + (tid >> 3)) * (TENC * FEAT) + (tid & 7)]);
    __syncthreads();
    asm volatile("barrier.cluster.arrive.aligned;" ::: "memory");
    asm volatile("barrier.cluster.wait.aligned;"   ::: "memory");

    // ---------------- thread mappings ---------------------------------------
    const int warp = tid >> 5, lane = tid & 31;
    const int col  = ((warp & 3) << 5) + lane;   // 0..127
    const int r0   = (warp >> 2) << 3;           // 0 or 8
    const int grow = tid >> 4;                   // gate-phase row 0..15
    const int gu   = (tid & 15) << 1;            // gate-phase unit (even) 0..30

    // precompute remote DSMEM addresses for the h exchange (both buffers, 8 peers)
    uint32_t hbase = smem_u32(hb);
    uint32_t haddr[2][CLUSTER];
#pragma unroll
    for (int b = 0; b < 2; ++b) {
        uint32_t loc = hbase + ((uint32_t)((b * MROWS + grow) * HD + (int)rank * 32 + gu)) * 4u;
#pragma unroll
        for (int p = 0; p < CLUSTER; ++p) {
            asm("mapa.shared::cluster.u32 %0, %1, %2;"
                : "=r"(haddr[b][p]) : "r"(loc), "r"(p));
        }
    }

    const ulonglong2* w2p = reinterpret_cast<const ulonglong2*>(wsm) + col;

    // ---------------- main sequential loop: 1024 encoder + 35 decoder -------
    for (int t = 0; t < TENC + TDEC; ++t) {
        const int  cur = t & 1, nxt = cur ^ 1;
        const bool enc = (t < TENC);

        // pulse prefetch for t+1 (held in register across the GEMV)
        float pnext = 0.f;
        if (tid < 128 && (t + 1) < TENC)
            pnext = __ldg(&pulse[(size_t)(b_base + (tid >> 3)) * (TENC * FEAT)
                                 + (size_t)(t + 1) * FEAT + (tid & 7)]);

        // ---- accumulator init: folded input projection ----
        unsigned long long accp[8];
        if (enc) {
            const float* pc = psm + cur * 128;
            float wcf[FEAT];
#pragma unroll
            for (int f = 0; f < FEAT; ++f) wcf[f] = wcs[f * NCOLS + col];
            const float bz = bes[col];
#pragma unroll
            for (int r = 0; r < 8; ++r) {
                float4 p0 = *reinterpret_cast<const float4*>(&pc[(r0 + r) * 8]);
                float4 p1 = *reinterpret_cast<const float4*>(&pc[(r0 + r) * 8 + 4]);
                float z = bz + p0.x * wcf[0] + p0.y * wcf[1] + p0.z * wcf[2] + p0.w * wcf[3]
                             + p1.x * wcf[4] + p1.y * wcf[5] + p1.z * wcf[6] + p1.w * wcf[7];
                accp[r] = pack2(z, 0.f);
            }
        } else {
            const float wd0 = wds[col], wd1 = wds[NCOLS + col], bz = bds[col];
#pragma unroll
            for (int r = 0; r < 8; ++r) {
                float z = bz + prd[(r0 + r) * 2 + 0] * wd0 + prd[(r0 + r) * 2 + 1] * wd1;
                accp[r] = pack2(z, 0.f);
            }
        }

        // ---- recurrent GEMV: z += h @ rk_slice (packed f32x2 FMA) ----
        const ulonglong2* h2p = reinterpret_cast<const ulonglong2*>(hb + cur * MROWS * HD);
#pragma unroll 4
        for (int kv = 0; kv < 64; ++kv) {
            ulonglong2 w2 = w2p[kv * NCOLS];
#pragma unroll
            for (int r = 0; r < 8; ++r) {
                ulonglong2 h2 = h2p[(r0 + r) * 64 + kv];
                accp[r] = ffma2(h2.x, w2.x, accp[r]);
                accp[r] = ffma2(h2.y, w2.y, accp[r]);
            }
        }
#pragma unroll
        for (int r = 0; r < 8; ++r) {
            float2 s = *reinterpret_cast<float2*>(&accp[r]);
            zsm[(r0 + r) * NCOLS + col] = s.x + s.y;
        }
        __syncthreads();

        // ---- gates + c/h update + DSMEM broadcast of h slice ----
        {
            const float* zr = zsm + grow * NCOLS;
            float2 zi = *reinterpret_cast<const float2*>(&zr[ 0 + gu]);
            float2 zf = *reinterpret_cast<const float2*>(&zr[32 + gu]);
            float2 zg = *reinterpret_cast<const float2*>(&zr[64 + gu]);
            float2 zo = *reinterpret_cast<const float2*>(&zr[96 + gu]);
            float2 c  = *reinterpret_cast<const float2*>(&csm[grow * 32 + gu]);

            float cn0 = sigf(zf.x) * c.x + sigf(zi.x) * tanhf(zg.x);
            float cn1 = sigf(zf.y) * c.y + sigf(zi.y) * tanhf(zg.y);
            float hn0 = sigf(zo.x) * tanhf(cn0);
            float hn1 = sigf(zo.y) * tanhf(cn1);
            *reinterpret_cast<float2*>(&csm[grow * 32 + gu]) = make_float2(cn0, cn1);

            unsigned long long hp = pack2(hn0, hn1);
#pragma unroll
            for (int p = 0; p < CLUSTER; ++p)
                asm volatile("st.shared::cluster.b64 [%0], %1;"
                             :: "r"(haddr[nxt][p]), "l"(hp) : "memory");
        }
        if (tid < 128 && (t + 1) < TENC) psm[nxt * 128 + tid] = pnext;

        // one cluster barrier per step (release/acquire orders the DSMEM stores)
        asm volatile("barrier.cluster.arrive.aligned;" ::: "memory");
        asm volatile("barrier.cluster.wait.aligned;"   ::: "memory");

        // ---- decoder epilogue: pred = h @ W_mlp + b_mlp ----
        if (!enc) {
            int s = t - TENC;
            if (tid < 32) {
                int row = tid >> 1, e = tid & 1;
                const float4* h4n =
                    reinterpret_cast<const float4*>(hb + nxt * MROWS * HD + row * HD);
                float acc = msc[e];
#pragma unroll 8
                for (int kv = 0; kv < 64; ++kv) {
                    float4 hv = h4n[kv];
                    acc += hv.x * wm[(4 * kv + 0) * 2 + e]
                         + hv.y * wm[(4 * kv + 1) * 2 + e]
                         + hv.z * wm[(4 * kv + 2) * 2 + e]
                         + hv.w * wm[(4 * kv + 3) * 2 + e];
                }
                prd[row * 2 + e] = acc;  // autoregressive carry (pre-scale)
                if (rank == 0)
                    out[((size_t)(b_base + row) * TDEC + s) * 2 + e] =
                        acc * msc[2 + e] + msc[4 + e];
            }
            __syncthreads();
        }
    }
}

// ---------------------------------------------------------------------------
// kernel_launch
// ---------------------------------------------------------------------------
extern "C" void kernel_launch(void* const* d_in, const int* in_sizes, int n_in,
                              void* d_out, int out_size)
{
    (void)in_sizes; (void)n_in; (void)out_size;
    const float* pulse       = (const float*)d_in[0];
    const float* bn_gamma    = (const float*)d_in[1];
    const float* bn_beta     = (const float*)d_in[2];
    const float* bn_mean     = (const float*)d_in[3];
    const float* bn_var      = (const float*)d_in[4];
    const float* W_pulse     = (const float*)d_in[5];
    const float* b_pulse     = (const float*)d_in[6];
    const float* lstm_k      = (const float*)d_in[7];
    const float* lstm_rk     = (const float*)d_in[8];
    const float* lstm_b      = (const float*)d_in[9];
    const float* embed_table = (const float*)d_in[10];
    const float* W_eis       = (const float*)d_in[11];
    const float* b_eis       = (const float*)d_in[12];
    const float* W_mlp       = (const float*)d_in[13];
    const float* b_mlp       = (const float*)d_in[14];
    const float* scale_w     = (const float*)d_in[15];
    const float* scale_b     = (const float*)d_in[16];
    float* out = (float*)d_out;

    cudaFuncSetAttribute(lstm_kernel,
                         cudaFuncAttributeMaxDynamicSharedMemorySize, SMEM_BYTES);

    precomp_kernel<<<4, 256>>>(bn_gamma, bn_beta, bn_mean, bn_var,
                               W_pulse, b_pulse, lstm_k, lstm_b, W_eis, b_eis);

    lstm_kernel<<<(BATCH / MROWS) * CLUSTER, NTHREADS, SMEM_BYTES>>>(
        pulse, lstm_rk, embed_table, W_mlp, b_mlp, scale_w, scale_b, out);
}

// round 11
// speedup vs baseline: 1.1103x; 1.1103x over previous
#include <cuda_runtime.h>
#include <cstdint>
#include <cstdio>

// ---------------------------------------------------------------------------
// Problem constants
// ---------------------------------------------------------------------------
#define BN_EPS   1e-3f
#define HD       256          // hidden dim
#define G4       1024         // 4*H
#define TENC     1024         // encoder steps
#define TDEC     35           // decoder steps
#define BATCH    256
#define FEAT     8

#define CLUSTER  8            // CTAs per cluster (N-partition of gates)
#define MROWS    16           // batch rows per cluster
#define NCOLS    128          // gate columns per CTA (32 units x 4 gates)
#define KQ       4            // k-split factor
#define KSL      64           // k per slice (HD/KQ)
#define NTHREADS 512          // 128 cols x 4 k-slices

// ---------------------------------------------------------------------------
// SMEM layout (float offsets)
// ---------------------------------------------------------------------------
#define OFF_H     0                       // 2 x 16 x 256 ping-pong h
#define OFF_Z     8192                    // 4 x 16 x 128 z partials
#define OFF_C     (OFF_Z + 8192)          // 512 (c state, 16 rows x 32 units)
#define OFF_P     (OFF_C + 512)           // 2 x 128 (pulse double buffer)
#define OFF_WM    (OFF_P + 256)           // 256 x 2 (W_mlp full)
#define OFF_PRED  (OFF_WM + 512)          // 16 x 2 (pred carry)
#define OFF_MISC  (OFF_PRED + 32)         // [0:2] b_mlp, [2:4] scale_w, [4:6] scale_b
#define SMEM_FLOATS (OFF_MISC + 32)
#define SMEM_BYTES  (SMEM_FLOATS * 4)     // ~69.3 KB

// ---------------------------------------------------------------------------
// Device scratch (precomputed folded weights)
// ---------------------------------------------------------------------------
__device__ float gWc[FEAT * G4];   // diag(a) * W_pulse @ lstm_k
__device__ float gBe[G4];          // folded encoder bias (incl lstm_b)
__device__ float gWd[2 * G4];      // W_eis @ lstm_k
__device__ float gBd[G4];          // b_eis @ lstm_k + lstm_b

// ---------------------------------------------------------------------------
// Precompute kernel: fold BN + pulse_embed + input projection into K=8 matrix,
// and decoder token embedding + input projection into K=2 matrix.
// ---------------------------------------------------------------------------
__global__ void precomp_kernel(const float* __restrict__ bn_gamma,
                               const float* __restrict__ bn_beta,
                               const float* __restrict__ bn_mean,
                               const float* __restrict__ bn_var,
                               const float* __restrict__ W_pulse,   // (8,256)
                               const float* __restrict__ b_pulse,   // (256)
                               const float* __restrict__ lstm_k,    // (256,1024)
                               const float* __restrict__ lstm_b,    // (1024)
                               const float* __restrict__ W_eis,     // (2,256)
                               const float* __restrict__ b_eis)     // (256)
{
    int g = blockIdx.x * blockDim.x + threadIdx.x;
    if (g >= G4) return;

    float a[FEAT], d[FEAT];
#pragma unroll
    for (int f = 0; f < FEAT; ++f) {
        a[f] = bn_gamma[f] * rsqrtf(bn_var[f] + BN_EPS);
        d[f] = bn_beta[f] - bn_mean[f] * a[f];
    }
    float wc[FEAT];
#pragma unroll
    for (int f = 0; f < FEAT; ++f) wc[f] = 0.f;
    float be = 0.f, wd0 = 0.f, wd1 = 0.f, bd = 0.f;

    for (int k = 0; k < HD; ++k) {
        float kk = lstm_k[k * G4 + g];
        float ev = b_pulse[k];
#pragma unroll
        for (int f = 0; f < FEAT; ++f) {
            float wp = W_pulse[f * HD + k];
            wc[f] += wp * kk;
            ev    += d[f] * wp;
        }
        be  += ev * kk;
        wd0 += W_eis[k] * kk;
        wd1 += W_eis[HD + k] * kk;
        bd  += b_eis[k] * kk;
    }
#pragma unroll
    for (int f = 0; f < FEAT; ++f) gWc[f * G4 + g] = a[f] * wc[f];
    gBe[g]      = be + lstm_b[g];
    gWd[g]      = wd0;
    gWd[G4 + g] = wd1;
    gBd[g]      = bd + lstm_b[g];
}

// ---------------------------------------------------------------------------
// Helpers
// ---------------------------------------------------------------------------
__device__ __forceinline__ unsigned long long ffma2(unsigned long long a,
                                                    unsigned long long b,
                                                    unsigned long long c) {
    unsigned long long d;
    asm("fma.rn.f32x2 %0, %1, %2, %3;" : "=l"(d) : "l"(a), "l"(b), "l"(c));
    return d;
}
__device__ __forceinline__ unsigned long long pack2(float lo, float hi) {
    float2 v = make_float2(lo, hi);
    return *reinterpret_cast<unsigned long long*>(&v);
}
__device__ __forceinline__ uint32_t smem_u32(const void* p) {
    uint32_t a;
    asm("{ .reg .u64 t; cvta.to.shared.u64 t, %1; cvt.u32.u64 %0, t; }"
        : "=r"(a) : "l"(p));
    return a;
}
__device__ __forceinline__ float sigf(float x) {
    return 1.f / (1.f + __expf(-x));
}

// ---------------------------------------------------------------------------
// Main persistent LSTM kernel. Cluster of 8 CTAs; each CTA owns 32 hidden
// units (all 4 gates) for 16 batch rows. Recurrent weights live in REGISTERS
// (64 floats/thread, k-split across 4 thread groups); h exchanged via DSMEM
// with ping-pong buffers; one cluster barrier per step.
// ---------------------------------------------------------------------------
extern __shared__ float smem[];

__global__ void __launch_bounds__(NTHREADS, 1) __cluster_dims__(CLUSTER, 1, 1)
lstm_kernel(const float* __restrict__ pulse,       // (256,1024,8)
            const float* __restrict__ lstm_rk,     // (256,1024)
            const float* __restrict__ embed_table, // (1,2)
            const float* __restrict__ W_mlp,       // (256,2)
            const float* __restrict__ b_mlp,       // (2)
            const float* __restrict__ scale_w,     // (2)
            const float* __restrict__ scale_b,     // (2)
            float* __restrict__ out)               // (256,35,2)
{
    const int tid = threadIdx.x;
    uint32_t rank;
    asm("mov.u32 %0, %%cluster_ctarank;" : "=r"(rank));
    const int cid    = blockIdx.x / CLUSTER;
    const int b_base = cid * MROWS;

    float* hb  = smem + OFF_H;
    float* zsm = smem + OFF_Z;
    float* csm = smem + OFF_C;
    float* psm = smem + OFF_P;
    float* wm  = smem + OFF_WM;
    float* prd = smem + OFF_PRED;
    float* msc = smem + OFF_MISC;

    // ---------------- thread mappings ---------------------------------------
    const int col  = tid & (NCOLS - 1);          // 0..127 (gate column)
    const int kq   = tid >> 7;                   // 0..3   (k slice)
    const int k0   = kq * KSL;                   // k slice base
    const int gcol = ((col >> 5) << 8) + (int)rank * 32 + (col & 31);
    const int grow = (tid & 255) >> 4;           // gate-phase row 0..15
    const int gu   = (tid & 15) << 1;            // gate-phase unit (even)

    // ---------------- prologue --------------------------------------------
    // recurrent weights -> registers: wp[j] = (rk[k0+2j][gcol], rk[k0+2j+1][gcol])
    unsigned long long wp[KSL / 2];
#pragma unroll
    for (int j = 0; j < KSL / 2; ++j) {
        float w0 = __ldg(&lstm_rk[(k0 + 2 * j)     * G4 + gcol]);
        float w1 = __ldg(&lstm_rk[(k0 + 2 * j + 1) * G4 + gcol]);
        wp[j] = pack2(w0, w1);
    }
    // folded input-projection constants -> registers
    float wcf[FEAT];
#pragma unroll
    for (int f = 0; f < FEAT; ++f) wcf[f] = __ldg(&gWc[f * G4 + gcol]);
    const float bes = __ldg(&gBe[gcol]);
    const float bds = __ldg(&gBd[gcol]);
    const float wd0 = __ldg(&gWd[gcol]);
    const float wd1 = __ldg(&gWd[G4 + gcol]);

    for (int i = tid; i < 512; i += NTHREADS) { wm[i] = W_mlp[i]; csm[i] = 0.f; }
    for (int i = tid; i < 2 * MROWS * HD; i += NTHREADS) hb[i] = 0.f;  // h0 = 0
    if (tid < 32) prd[tid] = embed_table[tid & 1];                     // tok0 carry
    if (tid < 2) { msc[tid] = b_mlp[tid]; msc[2 + tid] = scale_w[tid]; msc[4 + tid] = scale_b[tid]; }
    if (tid < 128)  // pulse for t=0
        psm[tid] = __ldg(&pulse[(size_t)(b_base + (tid >> 3)) * (TENC * FEAT) + (tid & 7)]);
    __syncthreads();
    asm volatile("barrier.cluster.arrive.aligned;" ::: "memory");
    asm volatile("barrier.cluster.wait.aligned;"   ::: "memory");

    const uint32_t hbase = smem_u32(hb);

    // ---------------- main sequential loop: 1024 encoder + 35 decoder -------
    for (int t = 0; t < TENC + TDEC; ++t) {
        const int  cur = t & 1, nxt = cur ^ 1;
        const bool enc = (t < TENC);

        // pulse prefetch for t+1 (held in register across the GEMV)
        float pnext = 0.f;
        if (tid < 128 && (t + 1) < TENC)
            pnext = __ldg(&pulse[(size_t)(b_base + (tid >> 3)) * (TENC * FEAT)
                                 + (size_t)(t + 1) * FEAT + (tid & 7)]);

        // ---- input projection for this thread's 4-row block (rows kq*4..+3)
        float zin[4];
        {
            const int rbase = kq << 2;
            if (enc) {
                const float* pc = psm + cur * 128;
#pragma unroll
                for (int rr = 0; rr < 4; ++rr) {
                    const float4 p0 = *reinterpret_cast<const float4*>(&pc[(rbase + rr) * 8]);
                    const float4 p1 = *reinterpret_cast<const float4*>(&pc[(rbase + rr) * 8 + 4]);
                    zin[rr] = bes + p0.x * wcf[0] + p0.y * wcf[1] + p0.z * wcf[2] + p0.w * wcf[3]
                                  + p1.x * wcf[4] + p1.y * wcf[5] + p1.z * wcf[6] + p1.w * wcf[7];
                }
            } else {
#pragma unroll
                for (int rr = 0; rr < 4; ++rr) {
                    const float2 pv = *reinterpret_cast<const float2*>(&prd[(rbase + rr) * 2]);
                    zin[rr] = bds + pv.x * wd0 + pv.y * wd1;
                }
            }
        }

        // ---- recurrent partial GEMV over this thread's k-slice -------------
        unsigned long long acc[MROWS];
#pragma unroll
        for (int r = 0; r < MROWS; ++r) acc[r] = 0ULL;

        // h[row][k] row-major; chunk c covers k = k0 + 4c .. +3 (one ulonglong2)
        const ulonglong2* h2p =
            reinterpret_cast<const ulonglong2*>(hb + cur * MROWS * HD) + kq * 16;
#pragma unroll
        for (int c = 0; c < 16; ++c) {
#pragma unroll
            for (int r = 0; r < MROWS; ++r) {
                ulonglong2 hv = h2p[r * 64 + c];          // broadcast across lanes
                acc[r] = ffma2(hv.x, wp[2 * c],     acc[r]);
                acc[r] = ffma2(hv.y, wp[2 * c + 1], acc[r]);
            }
        }
        // store partials (add input projection for owned rows)
#pragma unroll
        for (int r = 0; r < MROWS; ++r) {
            float2 v = *reinterpret_cast<float2*>(&acc[r]);
            float s = v.x + v.y;
            if ((r >> 2) == kq) s += zin[r & 3];
            zsm[(kq * MROWS + r) * NCOLS + col] = s;
        }
        __syncthreads();

        // ---- gates: sum 4 partials, c/h update, DSMEM broadcast -------------
        if (tid < 256) {
            float2 zi = make_float2(0.f, 0.f), zf = zi, zg = zi, zo = zi;
#pragma unroll
            for (int q = 0; q < KQ; ++q) {
                const float* zr = zsm + (q * MROWS + grow) * NCOLS;
                float2 a0 = *reinterpret_cast<const float2*>(&zr[ 0 + gu]);
                float2 a1 = *reinterpret_cast<const float2*>(&zr[32 + gu]);
                float2 a2 = *reinterpret_cast<const float2*>(&zr[64 + gu]);
                float2 a3 = *reinterpret_cast<const float2*>(&zr[96 + gu]);
                zi.x += a0.x; zi.y += a0.y;
                zf.x += a1.x; zf.y += a1.y;
                zg.x += a2.x; zg.y += a2.y;
                zo.x += a3.x; zo.y += a3.y;
            }
            float2 c = *reinterpret_cast<const float2*>(&csm[grow * 32 + gu]);
            float cn0 = sigf(zf.x) * c.x + sigf(zi.x) * tanhf(zg.x);
            float cn1 = sigf(zf.y) * c.y + sigf(zi.y) * tanhf(zg.y);
            float hn0 = sigf(zo.x) * tanhf(cn0);
            float hn1 = sigf(zo.y) * tanhf(cn1);
            *reinterpret_cast<float2*>(&csm[grow * 32 + gu]) = make_float2(cn0, cn1);

            unsigned long long hp = pack2(hn0, hn1);
            uint32_t loc = hbase +
                (uint32_t)(((nxt * MROWS + grow) * HD + (int)rank * 32 + gu) * 4);
#pragma unroll
            for (int p = 0; p < CLUSTER; ++p) {
                uint32_t ra;
                asm("mapa.shared::cluster.u32 %0, %1, %2;" : "=r"(ra) : "r"(loc), "r"(p));
                asm volatile("st.shared::cluster.b64 [%0], %1;"
                             :: "r"(ra), "l"(hp) : "memory");
            }
        }
        if (tid < 128 && (t + 1) < TENC) psm[nxt * 128 + tid] = pnext;

        // one cluster barrier per step (orders the DSMEM stores cluster-wide)
        asm volatile("barrier.cluster.arrive.aligned;" ::: "memory");
        asm volatile("barrier.cluster.wait.aligned;"   ::: "memory");

        // ---- decoder epilogue: pred = h @ W_mlp + b_mlp ----
        if (!enc) {
            int s = t - TENC;
            if (tid < 32) {
                int row = tid >> 1, e = tid & 1;
                const float4* h4n =
                    reinterpret_cast<const float4*>(hb + nxt * MROWS * HD + row * HD);
                float a = msc[e];
#pragma unroll 8
                for (int kv = 0; kv < 64; ++kv) {
                    float4 hv = h4n[kv];
                    a += hv.x * wm[(4 * kv + 0) * 2 + e]
                       + hv.y * wm[(4 * kv + 1) * 2 + e]
                       + hv.z * wm[(4 * kv + 2) * 2 + e]
                       + hv.w * wm[(4 * kv + 3) * 2 + e];
                }
                prd[row * 2 + e] = a;  // autoregressive carry (pre-scale)
                if (rank == 0)
                    out[((size_t)(b_base + row) * TDEC + s) * 2 + e] =
                        a * msc[2 + e] + msc[4 + e];
            }
            __syncthreads();
        }
    }
}

// ---------------------------------------------------------------------------
// kernel_launch
// ---------------------------------------------------------------------------
extern "C" void kernel_launch(void* const* d_in, const int* in_sizes, int n_in,
                              void* d_out, int out_size)
{
    (void)in_sizes; (void)n_in; (void)out_size;
    const float* pulse       = (const float*)d_in[0];
    const float* bn_gamma    = (const float*)d_in[1];
    const float* bn_beta     = (const float*)d_in[2];
    const float* bn_mean     = (const float*)d_in[3];
    const float* bn_var      = (const float*)d_in[4];
    const float* W_pulse     = (const float*)d_in[5];
    const float* b_pulse     = (const float*)d_in[6];
    const float* lstm_k      = (const float*)d_in[7];
    const float* lstm_rk     = (const float*)d_in[8];
    const float* lstm_b      = (const float*)d_in[9];
    const float* embed_table = (const float*)d_in[10];
    const float* W_eis       = (const float*)d_in[11];
    const float* b_eis       = (const float*)d_in[12];
    const float* W_mlp       = (const float*)d_in[13];
    const float* b_mlp       = (const float*)d_in[14];
    const float* scale_w     = (const float*)d_in[15];
    const float* scale_b     = (const float*)d_in[16];
    float* out = (float*)d_out;

    cudaFuncSetAttribute(lstm_kernel,
                         cudaFuncAttributeMaxDynamicSharedMemorySize, SMEM_BYTES);

    precomp_kernel<<<4, 256>>>(bn_gamma, bn_beta, bn_mean, bn_var,
                               W_pulse, b_pulse, lstm_k, lstm_b, W_eis, b_eis);

    lstm_kernel<<<(BATCH / MROWS) * CLUSTER, NTHREADS, SMEM_BYTES>>>(
        pulse, lstm_rk, embed_table, W_mlp, b_mlp, scale_w, scale_b, out);
}